// round 12
// baseline (speedup 1.0000x reference)
#include <cuda_runtime.h>
#include <math.h>

#define BB 4
#define NN 65536
#define KK 16
#define HH 64
#define TPB 256
#define NPTS (BB * NN)

// Scratch (device globals — no allocation).
__device__ float4 g_xyz4[NPTS];          // xyz repacked as float4 per point (4 MB)
__device__ float  g_feat[10 * NPTS];     // planar feat [10][B*N] (10.5 MB, L2-resident)
__device__ int    g_idx_is64;

// ---------------------------------------------------------------------------
// Transpose pos (B,3,N) -> g_xyz4[b*N+n] = {x,y,z,0}. Vectorized x4.
// Warp 0 of block 0 also detects idx dtype: for int64 values < 65536 every odd
// 32-bit word is zero; for int32 those words are random indices (P ~ 2^-1024).
// ---------------------------------------------------------------------------
__global__ __launch_bounds__(TPB) void transpose_pos_kernel(
    const float* __restrict__ pos, const unsigned* __restrict__ idxw)
{
    if (blockIdx.x == 0 && threadIdx.x < 32) {
        unsigned v = idxw[4 * threadIdx.x + 1] | idxw[4 * threadIdx.x + 3];
        unsigned any = __ballot_sync(0xffffffffu, v != 0u);
        if (threadIdx.x == 0) g_idx_is64 = (any == 0u) ? 1 : 0;
    }
    int t4 = blockIdx.x * TPB + threadIdx.x;       // one thread = 4 points
    if (t4 >= NPTS / 4) return;
    int b  = t4 >> 14;                             // NN/4 = 16384 groups/batch
    int n4 = t4 & 16383;
    const float4* pb = (const float4*)(pos + (size_t)b * 3 * NN);
    float4 x = pb[n4];
    float4 y = pb[(NN / 4) + n4];
    float4 z = pb[2 * (NN / 4) + n4];
    float4* o = g_xyz4 + ((size_t)b << 16) + ((size_t)n4 << 2);
    o[0] = make_float4(x.x, y.x, z.x, 0.0f);
    o[1] = make_float4(x.y, y.y, z.y, 0.0f);
    o[2] = make_float4(x.z, y.z, z.z, 0.0f);
    o[3] = make_float4(x.w, y.w, z.w, 0.0f);
}

// ---------------------------------------------------------------------------
// k1: per-point feature (gather + running max). No barriers, no phase 2.
// Writes feat planar: 10 coalesced STG.32 per point (1 wavefront each).
// ---------------------------------------------------------------------------
__global__ __launch_bounds__(TPB, 3) void feat_kernel(
    const void* __restrict__ idxv,
    const float* __restrict__ dist)
{
    int t = blockIdx.x * TPB + threadIdx.x;        // point id
    int base = (t >> 16) << 16;                    // batch base

    // all 16 neighbor indices upfront (dtype-adaptive)
    int id[KK];
    if (g_idx_is64 != 0) {
        const int4* q = (const int4*)((const char*)idxv + (size_t)t * (KK * 8));
#pragma unroll
        for (int i = 0; i < 8; i++) {
            int4 v = q[i];
            id[2 * i + 0] = v.x & (NN - 1);
            id[2 * i + 1] = v.z & (NN - 1);
        }
    } else {
        const int4* q = (const int4*)((const char*)idxv + (size_t)t * (KK * 4));
#pragma unroll
        for (int i = 0; i < 4; i++) {
            int4 v = q[i];
            id[4 * i + 0] = v.x & (NN - 1);
            id[4 * i + 1] = v.y & (NN - 1);
            id[4 * i + 2] = v.z & (NN - 1);
            id[4 * i + 3] = v.w & (NN - 1);
        }
    }

    float4 p = g_xyz4[t];

    float mnx = -INFINITY, mny = -INFINITY, mnz = -INFINITY;
    float mdx = -INFINITY, mdy = -INFINITY, mdz = -INFINITY;
#pragma unroll
    for (int k = 0; k < KK; k++) {
        float4 q = g_xyz4[base + id[k]];           // one LDG.128, L2-resident
        mnx = fmaxf(mnx, q.x);
        mny = fmaxf(mny, q.y);
        mnz = fmaxf(mnz, q.z);
        mdx = fmaxf(mdx, p.x - q.x);
        mdy = fmaxf(mdy, p.y - q.y);
        mdz = fmaxf(mdz, p.z - q.z);
    }

    const float4* d4 = (const float4*)(dist + (size_t)t * KK);
    float4 da = d4[0], db = d4[1];
    float m0 = fmaxf(fmaxf(da.x, da.y), fmaxf(da.z, da.w));
    float m1 = fmaxf(fmaxf(db.x, db.y), fmaxf(db.z, db.w));
    da = d4[2]; db = d4[3];
    float m2 = fmaxf(fmaxf(da.x, da.y), fmaxf(da.z, da.w));
    float m3 = fmaxf(fmaxf(db.x, db.y), fmaxf(db.z, db.w));
    float md = fmaxf(fmaxf(m0, m1), fmaxf(m2, m3));

    // planar coalesced feat stores
    g_feat[0 * NPTS + t] = p.x;
    g_feat[1 * NPTS + t] = p.y;
    g_feat[2 * NPTS + t] = p.z;
    g_feat[3 * NPTS + t] = mnx;
    g_feat[4 * NPTS + t] = mny;
    g_feat[5 * NPTS + t] = mnz;
    g_feat[6 * NPTS + t] = mdx;
    g_feat[7 * NPTS + t] = mdy;
    g_feat[8 * NPTS + t] = mdz;
    g_feat[9 * NPTS + t] = md;
}

// ---------------------------------------------------------------------------
// k2: matvec + bias + relu. 16 threads per point, c = tid & 15 fixed ->
// W columns hoisted to registers (cheap here: no gathers competing).
// feat reads hit L2 (10.5 MB resident). Stores: warp = 512B contiguous.
// ---------------------------------------------------------------------------
__global__ __launch_bounds__(TPB) void matvec_kernel(
    const float* __restrict__ W,
    const float* __restrict__ bias,
    float* __restrict__ out)
{
    int tid = threadIdx.x;
    int c   = tid & 15;                            // channel group (fixed)
    int lp  = tid >> 4;                            // local point 0..15
    long p  = (long)blockIdx.x * 16 + lp;          // global point

    float4 Wc[10];
#pragma unroll
    for (int j = 0; j < 10; j++)
        Wc[j] = ((const float4*)W)[j * 16 + c];
    float4 acc = ((const float4*)bias)[c];

#pragma unroll
    for (int j = 0; j < 10; j++) {
        float f = g_feat[(size_t)j * NPTS + p];    // L2 hit, 1 wf/warp
        acc.x = fmaf(f, Wc[j].x, acc.x);
        acc.y = fmaf(f, Wc[j].y, acc.y);
        acc.z = fmaf(f, Wc[j].z, acc.z);
        acc.w = fmaf(f, Wc[j].w, acc.w);
    }
    acc.x = fmaxf(acc.x, 0.0f);
    acc.y = fmaxf(acc.y, 0.0f);
    acc.z = fmaxf(acc.z, 0.0f);
    acc.w = fmaxf(acc.w, 0.0f);

    ((float4*)(out + p * HH))[c] = acc;
}

extern "C" void kernel_launch(void* const* d_in, const int* in_sizes, int n_in,
                              void* d_out, int out_size) {
    const float* pos  = (const float*)d_in[0];
    const void*  idx  = d_in[1];
    const float* dist = (const float*)d_in[2];
    const float* W    = (const float*)d_in[3];
    const float* bias = (const float*)d_in[4];
    float* out = (float*)d_out;

    transpose_pos_kernel<<<(NPTS / 4 + TPB - 1) / TPB, TPB>>>(pos, (const unsigned*)idx);
    feat_kernel<<<NPTS / TPB, TPB>>>(idx, dist);
    matvec_kernel<<<NPTS / 16, TPB>>>(W, bias, out);
}

// round 14
// speedup vs baseline: 1.5991x; 1.5991x over previous
#include <cuda_runtime.h>
#include <math.h>

#define BB 4
#define NN 65536
#define KK 16
#define HH 64
#define TPB 128

// Scratch: xyz repacked as float4 per point (w unused). 4*65536*16B = 4 MB.
__device__ float4 g_xyz4[BB * NN];
__device__ int g_idx_is64;

// ---- packed f32x2 helpers (sm_10x; ptxas never auto-fuses these) ----
__device__ __forceinline__ unsigned long long pk2(float lo, float hi) {
    unsigned long long d;
    asm("mov.b64 %0, {%1, %2};" : "=l"(d) : "f"(lo), "f"(hi));
    return d;
}
__device__ __forceinline__ unsigned long long ffma2(
    unsigned long long a, unsigned long long b, unsigned long long c) {
    unsigned long long d;
    asm("fma.rn.f32x2 %0, %1, %2, %3;" : "=l"(d) : "l"(a), "l"(b), "l"(c));
    return d;
}
__device__ __forceinline__ void upk2(unsigned long long v, float& lo, float& hi) {
    asm("mov.b64 {%0, %1}, %2;" : "=f"(lo), "=f"(hi) : "l"(v));
}

// Transpose pos (B,3,N) -> g_xyz4[b*N+n] = {x,y,z,0}, coalesced per coord.
// Warp 0 of block 0 also detects idx dtype: for int64 values < 65536 every odd
// 32-bit word is zero; for int32 those words are random indices (P ~ 2^-1024).
__global__ void transpose_pos_kernel(const float* __restrict__ pos,
                                     const unsigned* __restrict__ idxw) {
    if (blockIdx.x == 0 && threadIdx.x < 32) {
        unsigned v = idxw[4 * threadIdx.x + 1] | idxw[4 * threadIdx.x + 3];
        unsigned any = __ballot_sync(0xffffffffu, v != 0u);
        if (threadIdx.x == 0) g_idx_is64 = (any == 0u) ? 1 : 0;
    }
    int t = blockIdx.x * blockDim.x + threadIdx.x;
    if (t >= BB * NN) return;
    int b = t >> 16;
    int n = t & (NN - 1);
    const float* p = pos + (size_t)b * 3 * NN;
    float4 v;
    v.x = p[n];
    v.y = p[NN + n];
    v.z = p[2 * NN + n];
    v.w = 0.0f;
    g_xyz4[t] = v;
}

__global__ __launch_bounds__(TPB, 4) void point_embed_kernel(
    const void* __restrict__ idxv,
    const float* __restrict__ dist,
    const float* __restrict__ W,
    const float* __restrict__ bias,
    float* __restrict__ out)
{
    __shared__ float feat_s[TPB][10];

    int tid = threadIdx.x;
    int t = blockIdx.x * TPB + tid;   // this thread's point (phase 1)
    int base = (t >> 16) << 16;       // batch base

    // ---- all 16 neighbor indices upfront (dtype-adaptive), MLP=16 ----
    int id[KK];
    if (g_idx_is64 != 0) {
        const int4* q = (const int4*)((const char*)idxv + (size_t)t * (KK * 8));
#pragma unroll
        for (int i = 0; i < 8; i++) {
            int4 v = q[i];
            id[2 * i + 0] = v.x & (NN - 1);
            id[2 * i + 1] = v.z & (NN - 1);
        }
    } else {
        const int4* q = (const int4*)((const char*)idxv + (size_t)t * (KK * 4));
#pragma unroll
        for (int i = 0; i < 4; i++) {
            int4 v = q[i];
            id[4 * i + 0] = v.x & (NN - 1);
            id[4 * i + 1] = v.y & (NN - 1);
            id[4 * i + 2] = v.z & (NN - 1);
            id[4 * i + 3] = v.w & (NN - 1);
        }
    }

    float4 p = g_xyz4[t];

    float mnx = -INFINITY, mny = -INFINITY, mnz = -INFINITY;
    float mdx = -INFINITY, mdy = -INFINITY, mdz = -INFINITY;
#pragma unroll
    for (int k = 0; k < KK; k++) {
        float4 q = g_xyz4[base + id[k]];  // one LDG.128 per neighbor, L2-resident
        mnx = fmaxf(mnx, q.x);
        mny = fmaxf(mny, q.y);
        mnz = fmaxf(mnz, q.z);
        mdx = fmaxf(mdx, p.x - q.x);
        mdy = fmaxf(mdy, p.y - q.y);
        mdz = fmaxf(mdz, p.z - q.z);
    }

    const float4* d4 = (const float4*)(dist + (size_t)t * KK);
    float4 da = d4[0], db = d4[1];
    float m0 = fmaxf(fmaxf(da.x, da.y), fmaxf(da.z, da.w));
    float m1 = fmaxf(fmaxf(db.x, db.y), fmaxf(db.z, db.w));
    da = d4[2]; db = d4[3];
    float m2 = fmaxf(fmaxf(da.x, da.y), fmaxf(da.z, da.w));
    float m3 = fmaxf(fmaxf(db.x, db.y), fmaxf(db.z, db.w));
    float md = fmaxf(fmaxf(m0, m1), fmaxf(m2, m3));

    feat_s[tid][0] = p.x;  feat_s[tid][1] = p.y;  feat_s[tid][2] = p.z;
    feat_s[tid][3] = mnx;  feat_s[tid][4] = mny;  feat_s[tid][5] = mnz;
    feat_s[tid][6] = mdx;  feat_s[tid][7] = mdy;  feat_s[tid][8] = mdz;
    feat_s[tid][9] = md;

    // W columns hoisted as packed f32x2 pairs (channel group fixed per thread).
    int c = tid & 15;                  // which float4 of the 64 outputs
    unsigned long long Wxy[10], Wzw[10];
#pragma unroll
    for (int j = 0; j < 10; j++) {
        float4 w = ((const float4*)W)[j * 16 + c];
        Wxy[j] = pk2(w.x, w.y);
        Wzw[j] = pk2(w.z, w.w);
    }
    float4 bb = ((const float4*)bias)[c];
    unsigned long long Bxy = pk2(bb.x, bb.y);
    unsigned long long Bzw = pk2(bb.z, bb.w);

    __syncthreads();

    // ---- Phase 2: matvec + relu via fma.rn.f32x2, coalesced stores ----
    // 16 consecutive lanes cover one point's 64 channels; warp stores 512B
    // contiguous (4 L1 wavefronts).
    int sub = tid >> 4;                // 0..7
    long blk_base = (long)blockIdx.x * TPB;
#pragma unroll
    for (int it = 0; it < 16; it++) {
        int pl = it * 8 + sub;         // local point 0..127
        unsigned long long axy = Bxy, azw = Bzw;
#pragma unroll
        for (int j = 0; j < 10; j++) {
            float f = feat_s[pl][j];   // broadcast LDS (2 addrs/warp)
            unsigned long long ff = pk2(f, f);   // ALU pipe
            axy = ffma2(ff, Wxy[j], axy);        // 2 FMAs per instr
            azw = ffma2(ff, Wzw[j], azw);
        }
        float4 acc;
        upk2(axy, acc.x, acc.y);
        upk2(azw, acc.z, acc.w);
        acc.x = fmaxf(acc.x, 0.0f);
        acc.y = fmaxf(acc.y, 0.0f);
        acc.z = fmaxf(acc.z, 0.0f);
        acc.w = fmaxf(acc.w, 0.0f);
        ((float4*)(out + (blk_base + pl) * HH))[c] = acc;
    }
}

extern "C" void kernel_launch(void* const* d_in, const int* in_sizes, int n_in,
                              void* d_out, int out_size) {
    const float* pos  = (const float*)d_in[0];
    const void*  idx  = d_in[1];
    const float* dist = (const float*)d_in[2];
    const float* W    = (const float*)d_in[3];
    const float* bias = (const float*)d_in[4];
    float* out = (float*)d_out;

    transpose_pos_kernel<<<(BB * NN + 255) / 256, 256>>>(pos, (const unsigned*)idx);
    point_embed_kernel<<<(BB * NN) / TPB, TPB>>>(idx, dist, W, bias, out);
}